// round 1
// baseline (speedup 1.0000x reference)
#include <cuda_runtime.h>
#include <cuda_bf16.h>
#include <math.h>
#include <stdint.h>

// ---------------------------------------------------------------------------
// Problem constants
// ---------------------------------------------------------------------------
#define N0 100000
#define N1 50000
#define NE 200000
#define HID 128
#define NH 4
#define HD 32
#define NL 2
// relation (src_type, dst_type)
__constant__ int c_dummy; // keep nvcc happy about empty constant use

// ---------------------------------------------------------------------------
// Static device scratch (no allocations allowed)
// ---------------------------------------------------------------------------
__device__ float    g_q[(N0 + N1) * HID];      // q0 @0, q1 @N0*HID
__device__ float    g_kr[N0 * HID];            // relation key (max src count = N0)
__device__ float    g_vr[N0 * HID];            // relation value
__device__ float    g_agg[(N0 + N1) * HID];    // agg0 @0, agg1 @N0*HID
__device__ float    g_alpha[NE * NH];          // per-edge logits -> exp
__device__ unsigned g_amax[N0 * NH];           // encoded segment max
__device__ float    g_ssum[N0 * NH];           // segment sum
__device__ float    g_weff[2 * HID * HID + 2 * HID]; // wk_eff, wv_eff, bk_eff, bv_eff

// ---------------------------------------------------------------------------
// Helpers
// ---------------------------------------------------------------------------
__device__ __forceinline__ float gelu_exact(float x) {
    return 0.5f * x * (1.0f + erff(x * 0.7071067811865476f));
}
__device__ __forceinline__ unsigned enc_f(float f) {
    unsigned b = __float_as_uint(f);
    return (b & 0x80000000u) ? ~b : (b | 0x80000000u);
}
__device__ __forceinline__ float dec_f(unsigned k) {
    return __uint_as_float((k & 0x80000000u) ? (k ^ 0x80000000u) : ~k);
}

// ---------------------------------------------------------------------------
// GEMM: C[M,128] = epi( act(A)[M,128] @ B[128,128] + bias )
//   EPI: 0 = none, 1 = relu, 2 = skip-blend with hprev
//   ACTA: 0 = none, 1 = gelu on A elements
// Tiles: BM=64, BN=128, BK=32, 256 threads, 4x8 per thread.
// ---------------------------------------------------------------------------
#define BM 64
#define BN 128
#define BK 32

template <int EPI, int ACTA>
__global__ __launch_bounds__(256) void gemm_k128(
    const float* __restrict__ A, int lda,
    const float* __restrict__ B,
    const float* __restrict__ bias,
    float* __restrict__ C, int ldc, int M,
    const float* __restrict__ hprev, int ldh,
    const float* __restrict__ skipPtr)
{
    __shared__ float As[BK][68];   // padded: 68 floats keeps float4 alignment
    __shared__ float Bs[BK][BN];

    const int tid = threadIdx.x;
    const int row0 = blockIdx.x * BM;
    const int ty = tid >> 4;          // 0..15
    const int tx = tid & 15;          // 0..15

    const int ar = tid >> 3;          // 0..31
    const int ac = (tid & 7) << 2;    // 0,4,...,28

    float acc[4][8];
#pragma unroll
    for (int i = 0; i < 4; i++)
#pragma unroll
        for (int j = 0; j < 8; j++) acc[i][j] = 0.f;

    for (int k0 = 0; k0 < HID; k0 += BK) {
        // ---- load A tile (64 x 32), transposed into As[k][m]
#pragma unroll
        for (int half = 0; half < 2; half++) {
            int r = ar + half * 32;
            int grow = row0 + r;
            float4 a4 = make_float4(0.f, 0.f, 0.f, 0.f);
            if (grow < M)
                a4 = *reinterpret_cast<const float4*>(A + (size_t)grow * lda + k0 + ac);
            if (ACTA) {
                a4.x = gelu_exact(a4.x); a4.y = gelu_exact(a4.y);
                a4.z = gelu_exact(a4.z); a4.w = gelu_exact(a4.w);
            }
            As[ac + 0][r] = a4.x; As[ac + 1][r] = a4.y;
            As[ac + 2][r] = a4.z; As[ac + 3][r] = a4.w;
        }
        // ---- load B tile (32 x 128)
#pragma unroll
        for (int i = 0; i < 4; i++) {
            int idx = i * 256 + tid;          // float4 index, 0..1023
            int br = idx >> 5;                // 0..31
            int bc = (idx & 31) << 2;         // 0..124
            *reinterpret_cast<float4*>(&Bs[br][bc]) =
                *reinterpret_cast<const float4*>(B + (size_t)(k0 + br) * HID + bc);
        }
        __syncthreads();
#pragma unroll
        for (int kk = 0; kk < BK; kk++) {
            float4 a  = *reinterpret_cast<const float4*>(&As[kk][ty << 2]);
            float4 b0 = *reinterpret_cast<const float4*>(&Bs[kk][tx << 3]);
            float4 b1 = *reinterpret_cast<const float4*>(&Bs[kk][(tx << 3) + 4]);
            float av[4] = {a.x, a.y, a.z, a.w};
            float bv[8] = {b0.x, b0.y, b0.z, b0.w, b1.x, b1.y, b1.z, b1.w};
#pragma unroll
            for (int i = 0; i < 4; i++)
#pragma unroll
                for (int j = 0; j < 8; j++)
                    acc[i][j] = fmaf(av[i], bv[j], acc[i][j]);
        }
        __syncthreads();
    }

    float sgate = 0.f;
    if (EPI == 2) sgate = 1.f / (1.f + expf(-(*skipPtr)));

#pragma unroll
    for (int i = 0; i < 4; i++) {
        int grow = row0 + (ty << 2) + i;
        if (grow >= M) continue;
        int col = tx << 3;
        float v[8];
#pragma unroll
        for (int j = 0; j < 8; j++) {
            float t = acc[i][j] + bias[col + j];
            if (EPI == 1) t = fmaxf(t, 0.f);
            v[j] = t;
        }
        if (EPI == 2) {
            const float* hp = hprev + (size_t)grow * ldh + col;
#pragma unroll
            for (int j = 0; j < 8; j++)
                v[j] = sgate * v[j] + (1.f - sgate) * hp[j];
        }
        float* cp = C + (size_t)grow * ldc + col;
        *reinterpret_cast<float4*>(cp)     = make_float4(v[0], v[1], v[2], v[3]);
        *reinterpret_cast<float4*>(cp + 4) = make_float4(v[4], v[5], v[6], v[7]);
    }
}

// ---------------------------------------------------------------------------
// Fold per-head relation matrix into projection weight:
//   Weff[i, h*32+e] = sum_d W[i, h*32+d] * A[h, d, e]
//   beff[h*32+e]    = sum_d b[h*32+d]    * A[h, d, e]
// grid = 129 blocks (last one does bias), block = 128 threads
// ---------------------------------------------------------------------------
__global__ void combine_w_k(const float* __restrict__ W,
                            const float* __restrict__ bsrc,
                            const float* __restrict__ Arel,
                            float* __restrict__ Weff,
                            float* __restrict__ beff)
{
    int col = threadIdx.x;              // 0..127
    int h = col >> 5, e = col & 31;
    const float* Ah = Arel + h * HD * HD;   // A[h][d][e]
    int i = blockIdx.x;
    if (i < HID) {
        const float* wrow = W + (size_t)i * HID + h * HD;
        float acc = 0.f;
#pragma unroll
        for (int d = 0; d < HD; d++) acc = fmaf(wrow[d], Ah[d * HD + e], acc);
        Weff[(size_t)i * HID + col] = acc;
    } else {
        const float* brow = bsrc + h * HD;
        float acc = 0.f;
#pragma unroll
        for (int d = 0; d < HD; d++) acc = fmaf(brow[d], Ah[d * HD + e], acc);
        beff[col] = acc;
    }
}

// ---------------------------------------------------------------------------
// Edge stage (warp per edge)
// ---------------------------------------------------------------------------
__global__ void edge_alpha_k(const int* __restrict__ src, const int* __restrict__ dst,
                             const float* __restrict__ q, const float* __restrict__ kr,
                             const float* __restrict__ prel,
                             float* __restrict__ alpha, unsigned* __restrict__ amax,
                             int E)
{
    int gt = blockIdx.x * blockDim.x + threadIdx.x;
    int e = gt >> 5;
    if (e >= E) return;
    int lane = threadIdx.x & 31;
    int s = __ldg(&src[e]), d = __ldg(&dst[e]);
    float4 qv = reinterpret_cast<const float4*>(q)[(size_t)d * 32 + lane];
    float4 kv = reinterpret_cast<const float4*>(kr)[(size_t)s * 32 + lane];
    float acc = qv.x * kv.x + qv.y * kv.y + qv.z * kv.z + qv.w * kv.w;
    acc += __shfl_xor_sync(0xffffffffu, acc, 1);
    acc += __shfl_xor_sync(0xffffffffu, acc, 2);
    acc += __shfl_xor_sync(0xffffffffu, acc, 4);
    if ((lane & 7) == 0) {
        int h = lane >> 3;
        float a = acc * __ldg(&prel[h]) * 0.17677669529663689f; // 1/sqrt(32)
        alpha[(size_t)e * NH + h] = a;
        atomicMax(&amax[(size_t)d * NH + h], enc_f(a));
    }
}

__global__ void edge_exp_k(const int* __restrict__ dst,
                           const unsigned* __restrict__ amax,
                           float* __restrict__ alpha,
                           float* __restrict__ ssum, int E4)
{
    int idx = blockIdx.x * blockDim.x + threadIdx.x;
    if (idx >= E4) return;
    int e = idx >> 2, h = idx & 3;
    int d = __ldg(&dst[e]);
    float m = dec_f(amax[(size_t)d * NH + h]);
    float ex = expf(alpha[idx] - m);
    alpha[idx] = ex;
    atomicAdd(&ssum[(size_t)d * NH + h], ex);
}

__global__ void edge_msg_k(const int* __restrict__ src, const int* __restrict__ dst,
                           const float* __restrict__ vr,
                           const float* __restrict__ alpha,
                           const float* __restrict__ ssum,
                           float* __restrict__ agg, int E)
{
    int gt = blockIdx.x * blockDim.x + threadIdx.x;
    int e = gt >> 5;
    if (e >= E) return;
    int lane = threadIdx.x & 31;
    int s = __ldg(&src[e]), d = __ldg(&dst[e]);
    int h = lane >> 3;
    float coef = alpha[(size_t)e * NH + h] / (ssum[(size_t)d * NH + h] + 1e-16f);
    float4 v = reinterpret_cast<const float4*>(vr)[(size_t)s * 32 + lane];
    float* p = agg + (size_t)d * HID + lane * 4;
    asm volatile("red.global.add.v4.f32 [%0], {%1,%2,%3,%4};"
                 :: "l"(p), "f"(v.x * coef), "f"(v.y * coef),
                    "f"(v.z * coef), "f"(v.w * coef)
                 : "memory");
}

// ---------------------------------------------------------------------------
// Host orchestration
// ---------------------------------------------------------------------------
extern "C" void kernel_launch(void* const* d_in, const int* in_sizes, int n_in,
                              void* d_out, int out_size)
{
    const float* x0   = (const float*)d_in[0];
    const float* x1   = (const float*)d_in[1];
    const int* srcp[3] = {(const int*)d_in[2], (const int*)d_in[4], (const int*)d_in[6]};
    const int* dstp[3] = {(const int*)d_in[3], (const int*)d_in[5], (const int*)d_in[7]};
    const float* W_in = (const float*)d_in[8];
    const float* b_in = (const float*)d_in[9];
    const float* Wk   = (const float*)d_in[10];
    const float* bk   = (const float*)d_in[11];
    const float* Wq   = (const float*)d_in[12];
    const float* bq   = (const float*)d_in[13];
    const float* Wv   = (const float*)d_in[14];
    const float* bv   = (const float*)d_in[15];
    const float* Wa   = (const float*)d_in[16];
    const float* ba   = (const float*)d_in[17];
    const float* skip = (const float*)d_in[18];
    const float* a_rel = (const float*)d_in[19];
    const float* m_rel = (const float*)d_in[20];
    const float* p_rel = (const float*)d_in[21];

    float* out = (float*)d_out;
    const int OW = HID * (NL + 1);       // 384 output cols per node
    float* y0 = out;
    float* y1 = out + (size_t)N0 * OW;

    // scratch pointers
    float *q, *kr, *vr, *agg, *alpha, *ssum, *weff;
    unsigned* amax;
    cudaGetSymbolAddress((void**)&q,     g_q);
    cudaGetSymbolAddress((void**)&kr,    g_kr);
    cudaGetSymbolAddress((void**)&vr,    g_vr);
    cudaGetSymbolAddress((void**)&agg,   g_agg);
    cudaGetSymbolAddress((void**)&alpha, g_alpha);
    cudaGetSymbolAddress((void**)&amax,  g_amax);
    cudaGetSymbolAddress((void**)&ssum,  g_ssum);
    cudaGetSymbolAddress((void**)&weff,  g_weff);
    float* wk_eff = weff;
    float* wv_eff = weff + HID * HID;
    float* bk_eff = weff + 2 * HID * HID;
    float* bv_eff = weff + 2 * HID * HID + HID;

    const int etS[3] = {0, 1, 1};
    const int etD[3] = {1, 0, 1};
    const int Ncnt[2] = {N0, N1};

    // ---- input projection: h0 = relu(x0 @ W_in0 + b_in0) -> out cols [0,128)
    {
        dim3 g0((N0 + BM - 1) / BM), g1((N1 + BM - 1) / BM);
        gemm_k128<1, 0><<<g0, 256>>>(x0, HID, W_in, b_in, y0, OW, N0, nullptr, 0, nullptr);
        gemm_k128<1, 0><<<g1, 256>>>(x1, HID, W_in + HID * HID, b_in + HID,
                                     y1, OW, N1, nullptr, 0, nullptr);
    }

    for (int l = 0; l < NL; l++) {
        const float* h0 = y0 + l * HID;  // lda = OW
        const float* h1 = y1 + l * HID;
        const float* hbase[2] = {h0, h1};

        // Q projections for both types
        {
            dim3 g0((N0 + BM - 1) / BM), g1((N1 + BM - 1) / BM);
            gemm_k128<0, 0><<<g0, 256>>>(h0, OW, Wq + (size_t)(l * 2 + 0) * HID * HID,
                                         bq + (l * 2 + 0) * HID, q, HID, N0,
                                         nullptr, 0, nullptr);
            gemm_k128<0, 0><<<g1, 256>>>(h1, OW, Wq + (size_t)(l * 2 + 1) * HID * HID,
                                         bq + (l * 2 + 1) * HID, q + (size_t)N0 * HID,
                                         HID, N1, nullptr, 0, nullptr);
        }
        cudaMemsetAsync(agg, 0, (size_t)(N0 + N1) * HID * sizeof(float), 0);

        for (int r = 0; r < 3; r++) {
            int st = etS[r], dt = etD[r];
            int Ns = Ncnt[st], Nd = Ncnt[dt];
            const float* hs = hbase[st];

            combine_w_k<<<HID + 1, HID>>>(Wk + (size_t)(l * 2 + st) * HID * HID,
                                          bk + (l * 2 + st) * HID,
                                          a_rel + (size_t)(l * 3 + r) * NH * HD * HD,
                                          wk_eff, bk_eff);
            combine_w_k<<<HID + 1, HID>>>(Wv + (size_t)(l * 2 + st) * HID * HID,
                                          bv + (l * 2 + st) * HID,
                                          m_rel + (size_t)(l * 3 + r) * NH * HD * HD,
                                          wv_eff, bv_eff);

            dim3 gs((Ns + BM - 1) / BM);
            gemm_k128<0, 0><<<gs, 256>>>(hs, OW, wk_eff, bk_eff, kr, HID, Ns,
                                         nullptr, 0, nullptr);
            gemm_k128<0, 0><<<gs, 256>>>(hs, OW, wv_eff, bv_eff, vr, HID, Ns,
                                         nullptr, 0, nullptr);

            cudaMemsetAsync(amax, 0, (size_t)Nd * NH * sizeof(unsigned), 0);
            cudaMemsetAsync(ssum, 0, (size_t)Nd * NH * sizeof(float), 0);

            const float* qd = (dt == 0) ? q : q + (size_t)N0 * HID;
            float* aggd = (dt == 0) ? agg : agg + (size_t)N0 * HID;
            const float* pr = p_rel + (size_t)(l * 3 + r) * NH;

            int tpbE = 256;
            int nWarpThreads = NE * 32;
            edge_alpha_k<<<(nWarpThreads + tpbE - 1) / tpbE, tpbE>>>(
                srcp[r], dstp[r], qd, kr, pr, alpha, amax, NE);
            edge_exp_k<<<(NE * NH + tpbE - 1) / tpbE, tpbE>>>(
                dstp[r], amax, alpha, ssum, NE * NH);
            edge_msg_k<<<(nWarpThreads + tpbE - 1) / tpbE, tpbE>>>(
                srcp[r], dstp[r], vr, alpha, ssum, aggd, NE);
        }

        // output projection + skip blend, write out cols [(l+1)*128, (l+2)*128)
        {
            dim3 g0((N0 + BM - 1) / BM), g1((N1 + BM - 1) / BM);
            gemm_k128<2, 1><<<g0, 256>>>(agg, HID,
                                         Wa + (size_t)(l * 2 + 0) * HID * HID,
                                         ba + (l * 2 + 0) * HID,
                                         y0 + (l + 1) * HID, OW, N0,
                                         h0, OW, skip + l * 2 + 0);
            gemm_k128<2, 1><<<g1, 256>>>(agg + (size_t)N0 * HID, HID,
                                         Wa + (size_t)(l * 2 + 1) * HID * HID,
                                         ba + (l * 2 + 1) * HID,
                                         y1 + (l + 1) * HID, OW, N1,
                                         h1, OW, skip + l * 2 + 1);
        }
    }
}

// round 2
// speedup vs baseline: 1.1800x; 1.1800x over previous
#include <cuda_runtime.h>
#include <cuda_bf16.h>
#include <math.h>
#include <stdint.h>

// ---------------------------------------------------------------------------
// Problem constants
// ---------------------------------------------------------------------------
#define N0 100000
#define N1 50000
#define HID 128
#define NH 4
#define HD 32
#define NL 2

// qkv concat layouts
#define LD0 384   // type0: Q | K_r0 | V_r0
#define LD1 640   // type1: Q | K_r1 | V_r1 | K_r2 | V_r2

// ---------------------------------------------------------------------------
// Static device scratch
// ---------------------------------------------------------------------------
__device__ float    g_qkv0[(size_t)N0 * LD0];
__device__ float    g_qkv1[(size_t)N1 * LD1];
__device__ float    g_agg[(size_t)(N0 + N1) * HID];
__device__ float    g_alpha[200000 * NH];
__device__ unsigned g_amax[N0 * NH];
__device__ float    g_ssum[N0 * NH];
__device__ float    g_wcat0[HID * LD0];
__device__ float    g_wcat1[HID * LD1];
__device__ float    g_bcat0[LD0];
__device__ float    g_bcat1[LD1];

// ---------------------------------------------------------------------------
// Helpers
// ---------------------------------------------------------------------------
__device__ __forceinline__ float gelu_exact(float x) {
    return 0.5f * x * (1.0f + erff(x * 0.7071067811865476f));
}
__device__ __forceinline__ unsigned enc_f(float f) {
    unsigned b = __float_as_uint(f);
    return (b & 0x80000000u) ? ~b : (b | 0x80000000u);
}
__device__ __forceinline__ float dec_f(unsigned k) {
    return __uint_as_float((k & 0x80000000u) ? (k ^ 0x80000000u) : ~k);
}

// ---------------------------------------------------------------------------
// GEMM: C[M, :] (+= col tile) = epi( act(A)[M,128] @ B[128, N] + bias )
// 128x128x16 tiles, double-buffered, 256 threads, 8x8 per thread.
//   EPI: 0 none, 1 relu, 2 skip-blend   ACTA: 0 none, 1 gelu
// ---------------------------------------------------------------------------
#define GBM 128
#define GBN 128
#define GBK 16

template <int EPI, int ACTA>
__global__ __launch_bounds__(256, 2) void gemm128(
    const float* __restrict__ A, int lda,
    const float* __restrict__ B, int ldb,
    const float* __restrict__ bias,
    float* __restrict__ C, int ldc, int M,
    const float* __restrict__ hprev, int ldh,
    const float* __restrict__ skipPtr)
{
    __shared__ float As[2][GBK][GBM + 4];
    __shared__ float Bs[2][GBK][GBN];

    const int tid  = threadIdx.x;
    const int row0 = blockIdx.x * GBM;
    const int col0 = blockIdx.y * GBN;
    const int aIdx = tid * 2;               // 2 float4 per thread per tile

    float4 aReg[2], bReg[2];

    // ---- stage 0 load
    {
#pragma unroll
        for (int u = 0; u < 2; u++) {
            int idx = aIdx + u;
            int r = idx >> 2, c = (idx & 3) << 2;
            int grow = row0 + r;
            float4 v = make_float4(0.f, 0.f, 0.f, 0.f);
            if (grow < M) v = *reinterpret_cast<const float4*>(A + (size_t)grow * lda + c);
            if (ACTA) { v.x = gelu_exact(v.x); v.y = gelu_exact(v.y);
                        v.z = gelu_exact(v.z); v.w = gelu_exact(v.w); }
            aReg[u] = v;
            int br = idx >> 5, bc = (idx & 31) << 2;
            bReg[u] = *reinterpret_cast<const float4*>(B + (size_t)br * ldb + col0 + bc);
        }
#pragma unroll
        for (int u = 0; u < 2; u++) {
            int idx = aIdx + u;
            int r = idx >> 2, c = (idx & 3) << 2;
            As[0][c + 0][r] = aReg[u].x; As[0][c + 1][r] = aReg[u].y;
            As[0][c + 2][r] = aReg[u].z; As[0][c + 3][r] = aReg[u].w;
            int br = idx >> 5, bc = (idx & 31) << 2;
            *reinterpret_cast<float4*>(&Bs[0][br][bc]) = bReg[u];
        }
    }
    __syncthreads();

    float acc[8][8];
#pragma unroll
    for (int i = 0; i < 8; i++)
#pragma unroll
        for (int j = 0; j < 8; j++) acc[i][j] = 0.f;

    const int ty = tid >> 4;   // 0..15 -> rows ty*8..
    const int tx = tid & 15;   // 0..15 -> cols tx*8..

    int p = 0;
#pragma unroll
    for (int kt = 0; kt < HID / GBK; kt++) {
        if (kt < HID / GBK - 1) {
            int k0 = (kt + 1) * GBK;
#pragma unroll
            for (int u = 0; u < 2; u++) {
                int idx = aIdx + u;
                int r = idx >> 2, c = (idx & 3) << 2;
                int grow = row0 + r;
                float4 v = make_float4(0.f, 0.f, 0.f, 0.f);
                if (grow < M) v = *reinterpret_cast<const float4*>(A + (size_t)grow * lda + k0 + c);
                if (ACTA) { v.x = gelu_exact(v.x); v.y = gelu_exact(v.y);
                            v.z = gelu_exact(v.z); v.w = gelu_exact(v.w); }
                aReg[u] = v;
                int br = idx >> 5, bc = (idx & 31) << 2;
                bReg[u] = *reinterpret_cast<const float4*>(B + (size_t)(k0 + br) * ldb + col0 + bc);
            }
        }
#pragma unroll
        for (int kk = 0; kk < GBK; kk++) {
            float av[8], bv[8];
            *reinterpret_cast<float4*>(&av[0]) = *reinterpret_cast<const float4*>(&As[p][kk][ty * 8]);
            *reinterpret_cast<float4*>(&av[4]) = *reinterpret_cast<const float4*>(&As[p][kk][ty * 8 + 4]);
            *reinterpret_cast<float4*>(&bv[0]) = *reinterpret_cast<const float4*>(&Bs[p][kk][tx * 8]);
            *reinterpret_cast<float4*>(&bv[4]) = *reinterpret_cast<const float4*>(&Bs[p][kk][tx * 8 + 4]);
#pragma unroll
            for (int i = 0; i < 8; i++)
#pragma unroll
                for (int j = 0; j < 8; j++)
                    acc[i][j] = fmaf(av[i], bv[j], acc[i][j]);
        }
        if (kt < HID / GBK - 1) {
#pragma unroll
            for (int u = 0; u < 2; u++) {
                int idx = aIdx + u;
                int r = idx >> 2, c = (idx & 3) << 2;
                As[p ^ 1][c + 0][r] = aReg[u].x; As[p ^ 1][c + 1][r] = aReg[u].y;
                As[p ^ 1][c + 2][r] = aReg[u].z; As[p ^ 1][c + 3][r] = aReg[u].w;
                int br = idx >> 5, bc = (idx & 31) << 2;
                *reinterpret_cast<float4*>(&Bs[p ^ 1][br][bc]) = bReg[u];
            }
            __syncthreads();
            p ^= 1;
        }
    }

    float sgate = 0.f;
    if (EPI == 2) sgate = 1.f / (1.f + expf(-(*skipPtr)));

#pragma unroll
    for (int i = 0; i < 8; i++) {
        int grow = row0 + ty * 8 + i;
        if (grow >= M) continue;
        int col = col0 + tx * 8;
        float v[8];
#pragma unroll
        for (int j = 0; j < 8; j++) {
            float t = acc[i][j] + bias[col + j];
            if (EPI == 1) t = fmaxf(t, 0.f);
            v[j] = t;
        }
        if (EPI == 2) {
            const float* hp = hprev + (size_t)grow * ldh + col;
#pragma unroll
            for (int j = 0; j < 8; j++)
                v[j] = sgate * v[j] + (1.f - sgate) * hp[j];
        }
        float* cp = C + (size_t)grow * ldc + col;
        *reinterpret_cast<float4*>(cp)     = make_float4(v[0], v[1], v[2], v[3]);
        *reinterpret_cast<float4*>(cp + 4) = make_float4(v[4], v[5], v[6], v[7]);
    }
}

// ---------------------------------------------------------------------------
// Weight prep: fold per-head relation matrix into projection weight (into a
// concatenated buffer with leading dim ldDst), or plain copy for Q.
// ---------------------------------------------------------------------------
__global__ void combine_w_k(const float* __restrict__ W,
                            const float* __restrict__ bsrc,
                            const float* __restrict__ Arel,
                            float* __restrict__ Wdst,
                            float* __restrict__ bdst, int ldDst)
{
    int col = threadIdx.x;              // 0..127
    int h = col >> 5, e = col & 31;
    const float* Ah = Arel + h * HD * HD;
    int i = blockIdx.x;
    if (i < HID) {
        const float* wrow = W + (size_t)i * HID + h * HD;
        float acc = 0.f;
#pragma unroll
        for (int d = 0; d < HD; d++) acc = fmaf(wrow[d], Ah[d * HD + e], acc);
        Wdst[(size_t)i * ldDst + col] = acc;
    } else {
        const float* brow = bsrc + h * HD;
        float acc = 0.f;
#pragma unroll
        for (int d = 0; d < HD; d++) acc = fmaf(brow[d], Ah[d * HD + e], acc);
        bdst[col] = acc;
    }
}

__global__ void copy_w_k(const float* __restrict__ W,
                         const float* __restrict__ bsrc,
                         float* __restrict__ Wdst,
                         float* __restrict__ bdst, int ldDst)
{
    int col = threadIdx.x;
    int i = blockIdx.x;
    if (i < HID) Wdst[(size_t)i * ldDst + col] = W[(size_t)i * HID + col];
    else         bdst[col] = bsrc[col];
}

// ---------------------------------------------------------------------------
// Edge stage (warp per edge)
// ---------------------------------------------------------------------------
__global__ void edge_alpha_k(const int* __restrict__ src, const int* __restrict__ dst,
                             const float* __restrict__ q, int ldq,
                             const float* __restrict__ kr, int ldk,
                             const float* __restrict__ prel,
                             float* __restrict__ alpha, unsigned* __restrict__ amax,
                             int E)
{
    int gt = blockIdx.x * blockDim.x + threadIdx.x;
    int e = gt >> 5;
    if (e >= E) return;
    int lane = threadIdx.x & 31;
    int s = __ldg(&src[e]), d = __ldg(&dst[e]);
    float4 qv = *reinterpret_cast<const float4*>(q + (size_t)d * ldq + lane * 4);
    float4 kv = *reinterpret_cast<const float4*>(kr + (size_t)s * ldk + lane * 4);
    float acc = qv.x * kv.x + qv.y * kv.y + qv.z * kv.z + qv.w * kv.w;
    acc += __shfl_xor_sync(0xffffffffu, acc, 1);
    acc += __shfl_xor_sync(0xffffffffu, acc, 2);
    acc += __shfl_xor_sync(0xffffffffu, acc, 4);
    if ((lane & 7) == 0) {
        int h = lane >> 3;
        float a = acc * __ldg(&prel[h]) * 0.17677669529663689f; // 1/sqrt(32)
        alpha[(size_t)e * NH + h] = a;
        atomicMax(&amax[(size_t)d * NH + h], enc_f(a));
    }
}

__global__ void edge_exp_k(const int* __restrict__ dst,
                           const unsigned* __restrict__ amax,
                           float* __restrict__ alpha,
                           float* __restrict__ ssum, int E4)
{
    int idx = blockIdx.x * blockDim.x + threadIdx.x;
    if (idx >= E4) return;
    int e = idx >> 2, h = idx & 3;
    int d = __ldg(&dst[e]);
    float m = dec_f(amax[(size_t)d * NH + h]);
    float ex = expf(alpha[idx] - m);
    alpha[idx] = ex;
    atomicAdd(&ssum[(size_t)d * NH + h], ex);
}

__global__ void edge_msg_k(const int* __restrict__ src, const int* __restrict__ dst,
                           const float* __restrict__ vr, int ldv,
                           const float* __restrict__ alpha,
                           const float* __restrict__ ssum,
                           float* __restrict__ agg, int E)
{
    int gt = blockIdx.x * blockDim.x + threadIdx.x;
    int e = gt >> 5;
    if (e >= E) return;
    int lane = threadIdx.x & 31;
    int s = __ldg(&src[e]), d = __ldg(&dst[e]);
    int h = lane >> 3;
    float coef = alpha[(size_t)e * NH + h] / (ssum[(size_t)d * NH + h] + 1e-16f);
    float4 v = *reinterpret_cast<const float4*>(vr + (size_t)s * ldv + lane * 4);
    float* p = agg + (size_t)d * HID + lane * 4;
    asm volatile("red.global.add.v4.f32 [%0], {%1,%2,%3,%4};"
                 :: "l"(p), "f"(v.x * coef), "f"(v.y * coef),
                    "f"(v.z * coef), "f"(v.w * coef)
                 : "memory");
}

// ---------------------------------------------------------------------------
// Host orchestration
// ---------------------------------------------------------------------------
extern "C" void kernel_launch(void* const* d_in, const int* in_sizes, int n_in,
                              void* d_out, int out_size)
{
    const float* x0   = (const float*)d_in[0];
    const float* x1   = (const float*)d_in[1];
    const int* srcp[3] = {(const int*)d_in[2], (const int*)d_in[4], (const int*)d_in[6]};
    const int* dstp[3] = {(const int*)d_in[3], (const int*)d_in[5], (const int*)d_in[7]};
    const int  Ecnt[3] = {in_sizes[2], in_sizes[4], in_sizes[6]};
    const float* W_in = (const float*)d_in[8];
    const float* b_in = (const float*)d_in[9];
    const float* Wk   = (const float*)d_in[10];
    const float* bk   = (const float*)d_in[11];
    const float* Wq   = (const float*)d_in[12];
    const float* bq   = (const float*)d_in[13];
    const float* Wv   = (const float*)d_in[14];
    const float* bv   = (const float*)d_in[15];
    const float* Wa   = (const float*)d_in[16];
    const float* ba   = (const float*)d_in[17];
    const float* skip = (const float*)d_in[18];
    const float* a_rel = (const float*)d_in[19];
    const float* m_rel = (const float*)d_in[20];
    const float* p_rel = (const float*)d_in[21];

    float* out = (float*)d_out;
    const int OW = HID * (NL + 1);       // 384 output cols per node
    float* y0 = out;
    float* y1 = out + (size_t)N0 * OW;

    // scratch pointers
    float *qkv0, *qkv1, *agg, *alpha, *ssum, *wcat0, *wcat1, *bcat0, *bcat1;
    unsigned* amax;
    cudaGetSymbolAddress((void**)&qkv0,  g_qkv0);
    cudaGetSymbolAddress((void**)&qkv1,  g_qkv1);
    cudaGetSymbolAddress((void**)&agg,   g_agg);
    cudaGetSymbolAddress((void**)&alpha, g_alpha);
    cudaGetSymbolAddress((void**)&amax,  g_amax);
    cudaGetSymbolAddress((void**)&ssum,  g_ssum);
    cudaGetSymbolAddress((void**)&wcat0, g_wcat0);
    cudaGetSymbolAddress((void**)&wcat1, g_wcat1);
    cudaGetSymbolAddress((void**)&bcat0, g_bcat0);
    cudaGetSymbolAddress((void**)&bcat1, g_bcat1);

    const int etS[3] = {0, 1, 1};
    const int etD[3] = {1, 0, 1};
    const int Ncnt[2] = {N0, N1};

    const dim3 g0((N0 + GBM - 1) / GBM);
    const dim3 g1((N1 + GBM - 1) / GBM);

    // ---- input projection: h = relu(x @ W_in + b_in) -> out cols [0,128)
    gemm128<1, 0><<<g0, 256>>>(x0, HID, W_in, HID, b_in, y0, OW, N0, nullptr, 0, nullptr);
    gemm128<1, 0><<<g1, 256>>>(x1, HID, W_in + HID * HID, HID, b_in + HID,
                               y1, OW, N1, nullptr, 0, nullptr);

    for (int l = 0; l < NL; l++) {
        const float* h0 = y0 + l * HID;  // lda = OW
        const float* h1 = y1 + l * HID;

        // ---- build concatenated effective weights
        // type0: Q | K_r0 | V_r0
        copy_w_k   <<<HID + 1, HID>>>(Wq + (size_t)(l * 2 + 0) * HID * HID,
                                      bq + (l * 2 + 0) * HID, wcat0, bcat0, LD0);
        combine_w_k<<<HID + 1, HID>>>(Wk + (size_t)(l * 2 + 0) * HID * HID,
                                      bk + (l * 2 + 0) * HID,
                                      a_rel + (size_t)(l * 3 + 0) * NH * HD * HD,
                                      wcat0 + 128, bcat0 + 128, LD0);
        combine_w_k<<<HID + 1, HID>>>(Wv + (size_t)(l * 2 + 0) * HID * HID,
                                      bv + (l * 2 + 0) * HID,
                                      m_rel + (size_t)(l * 3 + 0) * NH * HD * HD,
                                      wcat0 + 256, bcat0 + 256, LD0);
        // type1: Q | K_r1 | V_r1 | K_r2 | V_r2
        copy_w_k   <<<HID + 1, HID>>>(Wq + (size_t)(l * 2 + 1) * HID * HID,
                                      bq + (l * 2 + 1) * HID, wcat1, bcat1, LD1);
        combine_w_k<<<HID + 1, HID>>>(Wk + (size_t)(l * 2 + 1) * HID * HID,
                                      bk + (l * 2 + 1) * HID,
                                      a_rel + (size_t)(l * 3 + 1) * NH * HD * HD,
                                      wcat1 + 128, bcat1 + 128, LD1);
        combine_w_k<<<HID + 1, HID>>>(Wv + (size_t)(l * 2 + 1) * HID * HID,
                                      bv + (l * 2 + 1) * HID,
                                      m_rel + (size_t)(l * 3 + 1) * NH * HD * HD,
                                      wcat1 + 256, bcat1 + 256, LD1);
        combine_w_k<<<HID + 1, HID>>>(Wk + (size_t)(l * 2 + 1) * HID * HID,
                                      bk + (l * 2 + 1) * HID,
                                      a_rel + (size_t)(l * 3 + 2) * NH * HD * HD,
                                      wcat1 + 384, bcat1 + 384, LD1);
        combine_w_k<<<HID + 1, HID>>>(Wv + (size_t)(l * 2 + 1) * HID * HID,
                                      bv + (l * 2 + 1) * HID,
                                      m_rel + (size_t)(l * 3 + 2) * NH * HD * HD,
                                      wcat1 + 512, bcat1 + 512, LD1);

        // ---- fused projections
        gemm128<0, 0><<<dim3(g0.x, LD0 / GBN), 256>>>(h0, OW, wcat0, LD0, bcat0,
                                                      qkv0, LD0, N0, nullptr, 0, nullptr);
        gemm128<0, 0><<<dim3(g1.x, LD1 / GBN), 256>>>(h1, OW, wcat1, LD1, bcat1,
                                                      qkv1, LD1, N1, nullptr, 0, nullptr);

        cudaMemsetAsync(agg, 0, (size_t)(N0 + N1) * HID * sizeof(float), 0);

        // relation pointer table
        const float* qd_tab[3]  = {qkv1,        qkv0,        qkv1};
        const int    ldq_tab[3] = {LD1,         LD0,         LD1};
        const float* kr_tab[3]  = {qkv0 + 128,  qkv1 + 128,  qkv1 + 384};
        const float* vr_tab[3]  = {qkv0 + 256,  qkv1 + 256,  qkv1 + 512};
        const int    lds_tab[3] = {LD0,         LD1,         LD1};

        for (int r = 0; r < 3; r++) {
            int dt = etD[r];
            int Nd = Ncnt[dt];
            int E  = Ecnt[r];

            cudaMemsetAsync(amax, 0, (size_t)Nd * NH * sizeof(unsigned), 0);
            cudaMemsetAsync(ssum, 0, (size_t)Nd * NH * sizeof(float), 0);

            float* aggd = (dt == 0) ? agg : agg + (size_t)N0 * HID;
            const float* pr = p_rel + (size_t)(l * 3 + r) * NH;

            int tpbE = 256;
            int nWT = E * 32;
            edge_alpha_k<<<(nWT + tpbE - 1) / tpbE, tpbE>>>(
                srcp[r], dstp[r], qd_tab[r], ldq_tab[r], kr_tab[r], lds_tab[r],
                pr, alpha, amax, E);
            edge_exp_k<<<(E * NH + tpbE - 1) / tpbE, tpbE>>>(
                dstp[r], amax, alpha, ssum, E * NH);
            edge_msg_k<<<(nWT + tpbE - 1) / tpbE, tpbE>>>(
                srcp[r], dstp[r], vr_tab[r], lds_tab[r], alpha, ssum, aggd, E);
        }

        // ---- output projection + skip blend
        gemm128<2, 1><<<g0, 256>>>(agg, HID,
                                   Wa + (size_t)(l * 2 + 0) * HID * HID, HID,
                                   ba + (l * 2 + 0) * HID,
                                   y0 + (l + 1) * HID, OW, N0,
                                   h0, OW, skip + l * 2 + 0);
        gemm128<2, 1><<<g1, 256>>>(agg + (size_t)N0 * HID, HID,
                                   Wa + (size_t)(l * 2 + 1) * HID * HID, HID,
                                   ba + (l * 2 + 1) * HID,
                                   y1 + (l + 1) * HID, OW, N1,
                                   h1, OW, skip + l * 2 + 1);
    }
}

// round 3
// speedup vs baseline: 1.7516x; 1.4844x over previous
#include <cuda_runtime.h>
#include <cuda_bf16.h>
#include <math.h>
#include <stdint.h>

// ---------------------------------------------------------------------------
// Problem constants
// ---------------------------------------------------------------------------
#define N0 100000
#define N1 50000
#define HID 128
#define NH 4
#define HD 32
#define NL 2

#define LD0 384   // type0: Q | K_r0 | V_r0
#define LD1 640   // type1: Q | K_r1 | V_r1 | K_r2 | V_r2

// ---------------------------------------------------------------------------
// Static device scratch
// ---------------------------------------------------------------------------
__device__ float    g_qkv0[(size_t)N0 * LD0];
__device__ float    g_qkv1[(size_t)N1 * LD1];
__device__ float    g_agg[(size_t)(N0 + N1) * HID];
__device__ float    g_alpha[200000 * NH];
__device__ float    g_ssum[N0 * NH];
__device__ float    g_wcat0[HID * LD0];
__device__ float    g_wcat1[HID * LD1];
__device__ float    g_bcat0[LD0];
__device__ float    g_bcat1[LD1];

// ---------------------------------------------------------------------------
// Helpers
// ---------------------------------------------------------------------------
__device__ __forceinline__ float gelu_exact(float x) {
    return 0.5f * x * (1.0f + erff(x * 0.7071067811865476f));
}
__device__ __forceinline__ unsigned f2tf32(float f) {
    unsigned u;
    asm("cvt.rna.tf32.f32 %0, %1;" : "=r"(u) : "f"(f));
    return u;
}
__device__ __forceinline__ void mma_tf32(float* c, const unsigned* a, const unsigned* b) {
    asm("mma.sync.aligned.m16n8k8.row.col.f32.tf32.tf32.f32 "
        "{%0,%1,%2,%3}, {%4,%5,%6,%7}, {%8,%9}, {%0,%1,%2,%3};"
        : "+f"(c[0]), "+f"(c[1]), "+f"(c[2]), "+f"(c[3])
        : "r"(a[0]), "r"(a[1]), "r"(a[2]), "r"(a[3]), "r"(b[0]), "r"(b[1]));
}

// ---------------------------------------------------------------------------
// Tensor-core TF32 GEMM: C[M, col tile] = epi( act(A)[M,128] @ B[128,N] + bias )
// Tiles: 128x128x16, double-buffered, 256 threads (8 warps, 2x4), warp=64x32.
//   EPI: 0 none, 1 relu, 2 skip-blend   ACTA: 0 none, 1 gelu
// ---------------------------------------------------------------------------
#define GBM 128
#define GBN 128
#define GBK 16

template <int EPI, int ACTA>
__global__ __launch_bounds__(256, 2) void gemm_tc(
    const float* __restrict__ A, int lda,
    const float* __restrict__ B, int ldb,
    const float* __restrict__ bias,
    float* __restrict__ C, int ldc, int M,
    const float* __restrict__ hprev, int ldh,
    const float* __restrict__ skipPtr)
{
    __shared__ unsigned As[2][GBK][132];      // [k][m]
    __shared__ unsigned Bs[2][GBN][20];       // [n][k]

    const int tid  = threadIdx.x;
    const int wid  = tid >> 5;
    const int lane = tid & 31;
    const int row0 = blockIdx.x * GBM;
    const int col0 = blockIdx.y * GBN;
    const int wm0  = (wid >> 2) * 64;
    const int wn0  = (wid & 3) * 32;
    const int g    = lane >> 2;    // group id 0..7
    const int tig  = lane & 3;     // thread in group

    // per-thread fill coordinates (2 float4 each for A and B per stage)
    const int idx0 = tid * 2;
    // A: rA = idx>>2 (row 0..127), cA = (idx&3)*4 (k 0..12)
    // B: kB = idx>>5 (k 0..15),  nB = (idx&31)*4 (n 0..124)

    float4 aF[2], bF[2];

    // ---- load stage 0
#pragma unroll
    for (int u = 0; u < 2; u++) {
        int idx = idx0 + u;
        int rA = idx >> 2, cA = (idx & 3) << 2;
        int grow = row0 + rA;
        float4 v = make_float4(0.f, 0.f, 0.f, 0.f);
        if (grow < M) v = *reinterpret_cast<const float4*>(A + (size_t)grow * lda + cA);
        if (ACTA) { v.x = gelu_exact(v.x); v.y = gelu_exact(v.y);
                    v.z = gelu_exact(v.z); v.w = gelu_exact(v.w); }
        aF[u] = v;
        int kB = idx >> 5, nB = (idx & 31) << 2;
        bF[u] = *reinterpret_cast<const float4*>(B + (size_t)kB * ldb + col0 + nB);
    }
#pragma unroll
    for (int u = 0; u < 2; u++) {
        int idx = idx0 + u;
        int rA = idx >> 2, cA = (idx & 3) << 2;
        As[0][cA + 0][rA] = f2tf32(aF[u].x);
        As[0][cA + 1][rA] = f2tf32(aF[u].y);
        As[0][cA + 2][rA] = f2tf32(aF[u].z);
        As[0][cA + 3][rA] = f2tf32(aF[u].w);
        int kB = idx >> 5, nB = (idx & 31) << 2;
        Bs[0][nB + 0][kB] = f2tf32(bF[u].x);
        Bs[0][nB + 1][kB] = f2tf32(bF[u].y);
        Bs[0][nB + 2][kB] = f2tf32(bF[u].z);
        Bs[0][nB + 3][kB] = f2tf32(bF[u].w);
    }
    __syncthreads();

    float acc[4][4][4];
#pragma unroll
    for (int i = 0; i < 4; i++)
#pragma unroll
        for (int j = 0; j < 4; j++)
#pragma unroll
            for (int q = 0; q < 4; q++) acc[i][j][q] = 0.f;

    int p = 0;
#pragma unroll
    for (int kt = 0; kt < HID / GBK; kt++) {
        if (kt < HID / GBK - 1) {
            int k0 = (kt + 1) * GBK;
#pragma unroll
            for (int u = 0; u < 2; u++) {
                int idx = idx0 + u;
                int rA = idx >> 2, cA = (idx & 3) << 2;
                int grow = row0 + rA;
                float4 v = make_float4(0.f, 0.f, 0.f, 0.f);
                if (grow < M) v = *reinterpret_cast<const float4*>(A + (size_t)grow * lda + k0 + cA);
                if (ACTA) { v.x = gelu_exact(v.x); v.y = gelu_exact(v.y);
                            v.z = gelu_exact(v.z); v.w = gelu_exact(v.w); }
                aF[u] = v;
                int kB = idx >> 5, nB = (idx & 31) << 2;
                bF[u] = *reinterpret_cast<const float4*>(B + (size_t)(k0 + kB) * ldb + col0 + nB);
            }
        }
        // compute on buffer p (2 k8-steps)
#pragma unroll
        for (int k8 = 0; k8 < 2; k8++) {
            const int kk = k8 * 8;
            unsigned aR[4][4], bR[4][2];
#pragma unroll
            for (int mt = 0; mt < 4; mt++) {
                int m = wm0 + mt * 16 + g;
                aR[mt][0] = As[p][kk + tig][m];
                aR[mt][1] = As[p][kk + tig][m + 8];
                aR[mt][2] = As[p][kk + tig + 4][m];
                aR[mt][3] = As[p][kk + tig + 4][m + 8];
            }
#pragma unroll
            for (int nt = 0; nt < 4; nt++) {
                int n = wn0 + nt * 8 + g;
                bR[nt][0] = Bs[p][n][kk + tig];
                bR[nt][1] = Bs[p][n][kk + tig + 4];
            }
#pragma unroll
            for (int mt = 0; mt < 4; mt++)
#pragma unroll
                for (int nt = 0; nt < 4; nt++)
                    mma_tf32(acc[mt][nt], aR[mt], bR[nt]);
        }
        if (kt < HID / GBK - 1) {
#pragma unroll
            for (int u = 0; u < 2; u++) {
                int idx = idx0 + u;
                int rA = idx >> 2, cA = (idx & 3) << 2;
                As[p ^ 1][cA + 0][rA] = f2tf32(aF[u].x);
                As[p ^ 1][cA + 1][rA] = f2tf32(aF[u].y);
                As[p ^ 1][cA + 2][rA] = f2tf32(aF[u].z);
                As[p ^ 1][cA + 3][rA] = f2tf32(aF[u].w);
                int kB = idx >> 5, nB = (idx & 31) << 2;
                Bs[p ^ 1][nB + 0][kB] = f2tf32(bF[u].x);
                Bs[p ^ 1][nB + 1][kB] = f2tf32(bF[u].y);
                Bs[p ^ 1][nB + 2][kB] = f2tf32(bF[u].z);
                Bs[p ^ 1][nB + 3][kB] = f2tf32(bF[u].w);
            }
            __syncthreads();
            p ^= 1;
        }
    }

    float sgate = 0.f;
    if (EPI == 2) sgate = 1.f / (1.f + expf(-(*skipPtr)));

#pragma unroll
    for (int mt = 0; mt < 4; mt++) {
#pragma unroll
        for (int rr = 0; rr < 2; rr++) {
            int grow = row0 + wm0 + mt * 16 + g + rr * 8;
            if (grow >= M) continue;
#pragma unroll
            for (int nt = 0; nt < 4; nt++) {
                int col = col0 + wn0 + nt * 8 + 2 * tig;
                float v0 = acc[mt][nt][rr * 2 + 0] + bias[col];
                float v1 = acc[mt][nt][rr * 2 + 1] + bias[col + 1];
                if (EPI == 1) { v0 = fmaxf(v0, 0.f); v1 = fmaxf(v1, 0.f); }
                if (EPI == 2) {
                    const float* hp = hprev + (size_t)grow * ldh + col;
                    v0 = sgate * v0 + (1.f - sgate) * hp[0];
                    v1 = sgate * v1 + (1.f - sgate) * hp[1];
                }
                *reinterpret_cast<float2*>(C + (size_t)grow * ldc + col) =
                    make_float2(v0, v1);
            }
        }
    }
}

// ---------------------------------------------------------------------------
// Fused weight prep: 8 sections per layer in one launch (grid.y = section).
// A==nullptr -> plain copy; else fold per-head relation matrix.
// ---------------------------------------------------------------------------
struct WPrepSec {
    const float* W; const float* b; const float* A;
    float* Wd; float* bd; int ld;
};
struct WPrep8 { WPrepSec s[8]; };

__global__ void prep_w_k(WPrep8 P)
{
    WPrepSec p = P.s[blockIdx.y];
    int col = threadIdx.x;             // 0..127
    int i = blockIdx.x;                // 0..128 (128 => bias)
    if (p.A == nullptr) {
        if (i < HID) p.Wd[(size_t)i * p.ld + col] = p.W[(size_t)i * HID + col];
        else         p.bd[col] = p.b[col];
        return;
    }
    int h = col >> 5, e = col & 31;
    const float* Ah = p.A + h * HD * HD;
    if (i < HID) {
        const float* wrow = p.W + (size_t)i * HID + h * HD;
        float acc = 0.f;
#pragma unroll
        for (int d = 0; d < HD; d++) acc = fmaf(wrow[d], Ah[d * HD + e], acc);
        p.Wd[(size_t)i * p.ld + col] = acc;
    } else {
        const float* brow = p.b + h * HD;
        float acc = 0.f;
#pragma unroll
        for (int d = 0; d < HD; d++) acc = fmaf(brow[d], Ah[d * HD + e], acc);
        p.bd[col] = acc;
    }
}

// ---------------------------------------------------------------------------
// Edge stage (warp per edge) — skip-max softmax: exp + segment-sum in pass 1
// ---------------------------------------------------------------------------
__global__ void edge_alpha_k(const int* __restrict__ src, const int* __restrict__ dst,
                             const float* __restrict__ q, int ldq,
                             const float* __restrict__ kr, int ldk,
                             const float* __restrict__ prel,
                             float* __restrict__ alpha, float* __restrict__ ssum,
                             int E)
{
    int gt = blockIdx.x * blockDim.x + threadIdx.x;
    int e = gt >> 5;
    if (e >= E) return;
    int lane = threadIdx.x & 31;
    int s = __ldg(&src[e]), d = __ldg(&dst[e]);
    float4 qv = *reinterpret_cast<const float4*>(q + (size_t)d * ldq + lane * 4);
    float4 kv = *reinterpret_cast<const float4*>(kr + (size_t)s * ldk + lane * 4);
    float acc = qv.x * kv.x + qv.y * kv.y + qv.z * kv.z + qv.w * kv.w;
    acc += __shfl_xor_sync(0xffffffffu, acc, 1);
    acc += __shfl_xor_sync(0xffffffffu, acc, 2);
    acc += __shfl_xor_sync(0xffffffffu, acc, 4);
    if ((lane & 7) == 0) {
        int h = lane >> 3;
        float a = acc * __ldg(&prel[h]) * 0.17677669529663689f; // 1/sqrt(32)
        float ex = expf(a);
        alpha[(size_t)e * NH + h] = ex;
        atomicAdd(&ssum[(size_t)d * NH + h], ex);
    }
}

__global__ void edge_msg_k(const int* __restrict__ src, const int* __restrict__ dst,
                           const float* __restrict__ vr, int ldv,
                           const float* __restrict__ alpha,
                           const float* __restrict__ ssum,
                           float* __restrict__ agg, int E)
{
    int gt = blockIdx.x * blockDim.x + threadIdx.x;
    int e = gt >> 5;
    if (e >= E) return;
    int lane = threadIdx.x & 31;
    int s = __ldg(&src[e]), d = __ldg(&dst[e]);
    int h = lane >> 3;
    float coef = alpha[(size_t)e * NH + h] / (ssum[(size_t)d * NH + h] + 1e-16f);
    float4 v = *reinterpret_cast<const float4*>(vr + (size_t)s * ldv + lane * 4);
    float* p = agg + (size_t)d * HID + lane * 4;
    asm volatile("red.global.add.v4.f32 [%0], {%1,%2,%3,%4};"
                 :: "l"(p), "f"(v.x * coef), "f"(v.y * coef),
                    "f"(v.z * coef), "f"(v.w * coef)
                 : "memory");
}

// ---------------------------------------------------------------------------
// Host orchestration
// ---------------------------------------------------------------------------
extern "C" void kernel_launch(void* const* d_in, const int* in_sizes, int n_in,
                              void* d_out, int out_size)
{
    const float* x0   = (const float*)d_in[0];
    const float* x1   = (const float*)d_in[1];
    const int* srcp[3] = {(const int*)d_in[2], (const int*)d_in[4], (const int*)d_in[6]};
    const int* dstp[3] = {(const int*)d_in[3], (const int*)d_in[5], (const int*)d_in[7]};
    const int  Ecnt[3] = {in_sizes[2], in_sizes[4], in_sizes[6]};
    const float* W_in = (const float*)d_in[8];
    const float* b_in = (const float*)d_in[9];
    const float* Wk   = (const float*)d_in[10];
    const float* bk   = (const float*)d_in[11];
    const float* Wq   = (const float*)d_in[12];
    const float* bq   = (const float*)d_in[13];
    const float* Wv   = (const float*)d_in[14];
    const float* bv   = (const float*)d_in[15];
    const float* Wa   = (const float*)d_in[16];
    const float* ba   = (const float*)d_in[17];
    const float* skip = (const float*)d_in[18];
    const float* a_rel = (const float*)d_in[19];
    const float* m_rel = (const float*)d_in[20];
    const float* p_rel = (const float*)d_in[21];

    float* out = (float*)d_out;
    const int OW = HID * (NL + 1);       // 384
    float* y0 = out;
    float* y1 = out + (size_t)N0 * OW;

    float *qkv0, *qkv1, *agg, *alpha, *ssum, *wcat0, *wcat1, *bcat0, *bcat1;
    cudaGetSymbolAddress((void**)&qkv0,  g_qkv0);
    cudaGetSymbolAddress((void**)&qkv1,  g_qkv1);
    cudaGetSymbolAddress((void**)&agg,   g_agg);
    cudaGetSymbolAddress((void**)&alpha, g_alpha);
    cudaGetSymbolAddress((void**)&ssum,  g_ssum);
    cudaGetSymbolAddress((void**)&wcat0, g_wcat0);
    cudaGetSymbolAddress((void**)&wcat1, g_wcat1);
    cudaGetSymbolAddress((void**)&bcat0, g_bcat0);
    cudaGetSymbolAddress((void**)&bcat1, g_bcat1);

    const int etD[3] = {1, 0, 1};
    const int Ncnt[2] = {N0, N1};

    const dim3 g0((N0 + GBM - 1) / GBM);
    const dim3 g1((N1 + GBM - 1) / GBM);

    // ---- input projection: h = relu(x @ W_in + b_in) -> out cols [0,128)
    gemm_tc<1, 0><<<g0, 256>>>(x0, HID, W_in, HID, b_in, y0, OW, N0, nullptr, 0, nullptr);
    gemm_tc<1, 0><<<g1, 256>>>(x1, HID, W_in + HID * HID, HID, b_in + HID,
                               y1, OW, N1, nullptr, 0, nullptr);

    for (int l = 0; l < NL; l++) {
        const float* h0 = y0 + l * HID;  // lda = OW
        const float* h1 = y1 + l * HID;

        // ---- fused weight prep (8 sections, one launch)
        WPrep8 P;
        const float* WkL0 = Wk + (size_t)(l * 2 + 0) * HID * HID;
        const float* WkL1 = Wk + (size_t)(l * 2 + 1) * HID * HID;
        const float* WvL0 = Wv + (size_t)(l * 2 + 0) * HID * HID;
        const float* WvL1 = Wv + (size_t)(l * 2 + 1) * HID * HID;
        const float* ar0 = a_rel + (size_t)(l * 3 + 0) * NH * HD * HD;
        const float* ar1 = a_rel + (size_t)(l * 3 + 1) * NH * HD * HD;
        const float* ar2 = a_rel + (size_t)(l * 3 + 2) * NH * HD * HD;
        const float* mr0 = m_rel + (size_t)(l * 3 + 0) * NH * HD * HD;
        const float* mr1 = m_rel + (size_t)(l * 3 + 1) * NH * HD * HD;
        const float* mr2 = m_rel + (size_t)(l * 3 + 2) * NH * HD * HD;
        P.s[0] = {Wq + (size_t)(l*2+0)*HID*HID, bq + (l*2+0)*HID, nullptr, wcat0,       bcat0,       LD0};
        P.s[1] = {WkL0, bk + (l*2+0)*HID, ar0, wcat0 + 128, bcat0 + 128, LD0};
        P.s[2] = {WvL0, bv + (l*2+0)*HID, mr0, wcat0 + 256, bcat0 + 256, LD0};
        P.s[3] = {Wq + (size_t)(l*2+1)*HID*HID, bq + (l*2+1)*HID, nullptr, wcat1,       bcat1,       LD1};
        P.s[4] = {WkL1, bk + (l*2+1)*HID, ar1, wcat1 + 128, bcat1 + 128, LD1};
        P.s[5] = {WvL1, bv + (l*2+1)*HID, mr1, wcat1 + 256, bcat1 + 256, LD1};
        P.s[6] = {WkL1, bk + (l*2+1)*HID, ar2, wcat1 + 384, bcat1 + 384, LD1};
        P.s[7] = {WvL1, bv + (l*2+1)*HID, mr2, wcat1 + 512, bcat1 + 512, LD1};
        prep_w_k<<<dim3(HID + 1, 8), HID>>>(P);

        // ---- fused projections
        gemm_tc<0, 0><<<dim3(g0.x, LD0 / GBN), 256>>>(h0, OW, wcat0, LD0, bcat0,
                                                      qkv0, LD0, N0, nullptr, 0, nullptr);
        gemm_tc<0, 0><<<dim3(g1.x, LD1 / GBN), 256>>>(h1, OW, wcat1, LD1, bcat1,
                                                      qkv1, LD1, N1, nullptr, 0, nullptr);

        cudaMemsetAsync(agg, 0, (size_t)(N0 + N1) * HID * sizeof(float), 0);

        const float* qd_tab[3]  = {qkv1,        qkv0,        qkv1};
        const int    ldq_tab[3] = {LD1,         LD0,         LD1};
        const float* kr_tab[3]  = {qkv0 + 128,  qkv1 + 128,  qkv1 + 384};
        const float* vr_tab[3]  = {qkv0 + 256,  qkv1 + 256,  qkv1 + 512};
        const int    lds_tab[3] = {LD0,         LD1,         LD1};

        for (int r = 0; r < 3; r++) {
            int dt = etD[r];
            int Nd = Ncnt[dt];
            int E  = Ecnt[r];

            cudaMemsetAsync(ssum, 0, (size_t)Nd * NH * sizeof(float), 0);

            float* aggd = (dt == 0) ? agg : agg + (size_t)N0 * HID;
            const float* pr = p_rel + (size_t)(l * 3 + r) * NH;

            int tpbE = 256;
            int nWT = E * 32;
            edge_alpha_k<<<(nWT + tpbE - 1) / tpbE, tpbE>>>(
                srcp[r], dstp[r], qd_tab[r], ldq_tab[r], kr_tab[r], lds_tab[r],
                pr, alpha, ssum, E);
            edge_msg_k<<<(nWT + tpbE - 1) / tpbE, tpbE>>>(
                srcp[r], dstp[r], vr_tab[r], lds_tab[r], alpha, ssum, aggd, E);
        }

        // ---- output projection + skip blend
        gemm_tc<2, 1><<<g0, 256>>>(agg, HID,
                                   Wa + (size_t)(l * 2 + 0) * HID * HID, HID,
                                   ba + (l * 2 + 0) * HID,
                                   y0 + (l + 1) * HID, OW, N0,
                                   h0, OW, skip + l * 2 + 0);
        gemm_tc<2, 1><<<g1, 256>>>(agg + (size_t)N0 * HID, HID,
                                   Wa + (size_t)(l * 2 + 1) * HID * HID, HID,
                                   ba + (l * 2 + 1) * HID,
                                   y1 + (l + 1) * HID, OW, N1,
                                   h1, OW, skip + l * 2 + 1);
    }
}

// round 4
// speedup vs baseline: 2.4875x; 1.4201x over previous
#include <cuda_runtime.h>
#include <cuda_bf16.h>
#include <math.h>
#include <stdint.h>

// ---------------------------------------------------------------------------
// Problem constants
// ---------------------------------------------------------------------------
#define N0 100000
#define N1 50000
#define HID 128
#define NH 4
#define HD 32
#define NL 2

#define LD0 384   // type0: Q | K_r0 | V_r0
#define LD1 640   // type1: Q | K_r1 | V_r1 | K_r2 | V_r2

// ---------------------------------------------------------------------------
// Static device scratch
// ---------------------------------------------------------------------------
__device__ float    g_qkv0[(size_t)N0 * LD0];
__device__ float    g_qkv1[(size_t)N1 * LD1];
__device__ float    g_agg[(size_t)(N0 + N1) * HID];
__device__ float    g_alpha[200000 * NH];
__device__ float    g_ssum[N0 * NH];
__device__ float    g_wcat0[HID * LD0];
__device__ float    g_wcat1[HID * LD1];
__device__ float    g_bcat0[LD0];
__device__ float    g_bcat1[LD1];

// ---------------------------------------------------------------------------
// Helpers
// ---------------------------------------------------------------------------
__device__ __forceinline__ float gelu_exact(float x) {
    return 0.5f * x * (1.0f + erff(x * 0.7071067811865476f));
}
__device__ __forceinline__ unsigned f2tf32(float f) {
    unsigned u;
    asm("cvt.rna.tf32.f32 %0, %1;" : "=r"(u) : "f"(f));
    return u;
}
__device__ __forceinline__ void mma_tf32(float* c, const unsigned* a, const unsigned* b) {
    asm("mma.sync.aligned.m16n8k8.row.col.f32.tf32.tf32.f32 "
        "{%0,%1,%2,%3}, {%4,%5,%6,%7}, {%8,%9}, {%0,%1,%2,%3};"
        : "+f"(c[0]), "+f"(c[1]), "+f"(c[2]), "+f"(c[3])
        : "r"(a[0]), "r"(a[1]), "r"(a[2]), "r"(a[3]), "r"(b[0]), "r"(b[1]));
}
__device__ __forceinline__ void cpa16(float* dst, const float* src) {
    unsigned d = (unsigned)__cvta_generic_to_shared(dst);
    asm volatile("cp.async.cg.shared.global [%0], [%1], 16;" :: "r"(d), "l"(src));
}
__device__ __forceinline__ void cp_commit() {
    asm volatile("cp.async.commit_group;");
}
template <int N>
__device__ __forceinline__ void cp_wait() {
    asm volatile("cp.async.wait_group %0;" :: "n"(N));
}

// ---------------------------------------------------------------------------
// TF32 tensor-core GEMM with cp.async 3-stage pipeline.
// C[M, col tile] = epi( A[M,128] @ B[128,N] + bias )
// 128x128x16 tiles, 256 threads (8 warps 2x4), warp tile 64x32.
// Smem: A stage [128][20] (pad 20 = conflict-free), B stage [16][136].
//   EPI: 0 none, 1 relu, 2 skip-blend with hprev
// ---------------------------------------------------------------------------
#define GBM 128
#define GBN 128
#define AS_LD 20
#define BS_LD 136
#define A_STG (128 * AS_LD)
#define B_STG (16 * BS_LD)
#define GEMM_SMEM (3 * (A_STG + B_STG) * 4)

template <int EPI>
__global__ __launch_bounds__(256, 2) void gemm_tc(
    const float* __restrict__ A, int lda,
    const float* __restrict__ B, int ldb,
    const float* __restrict__ bias,
    float* __restrict__ C, int ldc, int M,
    const float* __restrict__ hprev, int ldh,
    const float* __restrict__ skipPtr)
{
    extern __shared__ float smemf[];
    float* AsBase = smemf;                   // 3 stages of [128][AS_LD]
    float* BsBase = smemf + 3 * A_STG;       // 3 stages of [16][BS_LD]

    const int tid  = threadIdx.x;
    const int wid  = tid >> 5;
    const int lane = tid & 31;
    const int row0 = blockIdx.x * GBM;
    const int col0 = blockIdx.y * GBN;
    const int wm0  = (wid >> 2) * 64;
    const int wn0  = (wid & 3) * 32;
    const int g    = lane >> 2;
    const int tig  = lane & 3;

    // per-thread cp.async chunk coordinates (2 chunks A + 2 chunks B / stage)
    // A chunk c: r = c>>2 (row), kc = (c&3)*4 ; B chunk c: kr = c>>5, nc = (c&31)*4
    auto stage_load = [&](int s, int k0) {
#pragma unroll
        for (int u = 0; u < 2; u++) {
            int c = tid + u * 256;
            int r = c >> 2, kc = (c & 3) << 2;
            int grow = row0 + r; if (grow >= M) grow = M - 1;
            cpa16(AsBase + s * A_STG + r * AS_LD + kc,
                  A + (size_t)grow * lda + k0 + kc);
            int kr = c >> 5, nc = (c & 31) << 2;
            cpa16(BsBase + s * B_STG + kr * BS_LD + nc,
                  B + (size_t)(k0 + kr) * ldb + col0 + nc);
        }
    };

    stage_load(0, 0);  cp_commit();
    stage_load(1, 16); cp_commit();

    float acc[4][4][4];
#pragma unroll
    for (int i = 0; i < 4; i++)
#pragma unroll
        for (int j = 0; j < 4; j++)
#pragma unroll
            for (int q = 0; q < 4; q++) acc[i][j][q] = 0.f;

#pragma unroll
    for (int kt = 0; kt < 8; kt++) {
        cp_wait<1>();
        __syncthreads();
        if (kt + 2 < 8) stage_load((kt + 2) % 3, (kt + 2) * 16);
        cp_commit();

        const float* Ast = AsBase + (kt % 3) * A_STG;
        const float* Bst = BsBase + (kt % 3) * B_STG;
#pragma unroll
        for (int k8 = 0; k8 < 2; k8++) {
            const int kk = k8 * 8;
            unsigned aR[4][4], bR[4][2];
#pragma unroll
            for (int mt = 0; mt < 4; mt++) {
                int m = wm0 + mt * 16 + g;
                aR[mt][0] = f2tf32(Ast[(size_t)m * AS_LD + kk + tig]);
                aR[mt][1] = f2tf32(Ast[(size_t)(m + 8) * AS_LD + kk + tig]);
                aR[mt][2] = f2tf32(Ast[(size_t)m * AS_LD + kk + tig + 4]);
                aR[mt][3] = f2tf32(Ast[(size_t)(m + 8) * AS_LD + kk + tig + 4]);
            }
#pragma unroll
            for (int nt = 0; nt < 4; nt++) {
                int n = wn0 + nt * 8 + g;
                bR[nt][0] = f2tf32(Bst[(size_t)(kk + tig) * BS_LD + n]);
                bR[nt][1] = f2tf32(Bst[(size_t)(kk + tig + 4) * BS_LD + n]);
            }
#pragma unroll
            for (int mt = 0; mt < 4; mt++)
#pragma unroll
                for (int nt = 0; nt < 4; nt++)
                    mma_tf32(acc[mt][nt], aR[mt], bR[nt]);
        }
        __syncthreads();
    }

    float sgate = 0.f;
    if (EPI == 2) sgate = 1.f / (1.f + expf(-(*skipPtr)));

#pragma unroll
    for (int mt = 0; mt < 4; mt++) {
#pragma unroll
        for (int rr = 0; rr < 2; rr++) {
            int grow = row0 + wm0 + mt * 16 + g + rr * 8;
            if (grow >= M) continue;
#pragma unroll
            for (int nt = 0; nt < 4; nt++) {
                int col = col0 + wn0 + nt * 8 + 2 * tig;
                float v0 = acc[mt][nt][rr * 2 + 0] + bias[col];
                float v1 = acc[mt][nt][rr * 2 + 1] + bias[col + 1];
                if (EPI == 1) { v0 = fmaxf(v0, 0.f); v1 = fmaxf(v1, 0.f); }
                if (EPI == 2) {
                    const float* hp = hprev + (size_t)grow * ldh + col;
                    v0 = sgate * v0 + (1.f - sgate) * hp[0];
                    v1 = sgate * v1 + (1.f - sgate) * hp[1];
                }
                *reinterpret_cast<float2*>(C + (size_t)grow * ldc + col) =
                    make_float2(v0, v1);
            }
        }
    }
}

// ---------------------------------------------------------------------------
// Elementwise gelu (in place), float4 vectorized
// ---------------------------------------------------------------------------
__global__ void gelu_k(float* __restrict__ a, int n4)
{
    int i = blockIdx.x * blockDim.x + threadIdx.x;
    if (i >= n4) return;
    float4 v = reinterpret_cast<float4*>(a)[i];
    v.x = gelu_exact(v.x); v.y = gelu_exact(v.y);
    v.z = gelu_exact(v.z); v.w = gelu_exact(v.w);
    reinterpret_cast<float4*>(a)[i] = v;
}

// ---------------------------------------------------------------------------
// Fused weight prep: 8 sections per layer in one launch (grid.y = section).
// ---------------------------------------------------------------------------
struct WPrepSec {
    const float* W; const float* b; const float* A;
    float* Wd; float* bd; int ld;
};
struct WPrep8 { WPrepSec s[8]; };

__global__ void prep_w_k(WPrep8 P)
{
    WPrepSec p = P.s[blockIdx.y];
    int col = threadIdx.x;
    int i = blockIdx.x;
    if (p.A == nullptr) {
        if (i < HID) p.Wd[(size_t)i * p.ld + col] = p.W[(size_t)i * HID + col];
        else         p.bd[col] = p.b[col];
        return;
    }
    int h = col >> 5, e = col & 31;
    const float* Ah = p.A + h * HD * HD;
    if (i < HID) {
        const float* wrow = p.W + (size_t)i * HID + h * HD;
        float acc = 0.f;
#pragma unroll
        for (int d = 0; d < HD; d++) acc = fmaf(wrow[d], Ah[d * HD + e], acc);
        p.Wd[(size_t)i * p.ld + col] = acc;
    } else {
        const float* brow = p.b + h * HD;
        float acc = 0.f;
#pragma unroll
        for (int d = 0; d < HD; d++) acc = fmaf(brow[d], Ah[d * HD + e], acc);
        p.bd[col] = acc;
    }
}

// ---------------------------------------------------------------------------
// Edge stage (warp per edge) — skip-max softmax
// ---------------------------------------------------------------------------
__global__ void edge_alpha_k(const int* __restrict__ src, const int* __restrict__ dst,
                             const float* __restrict__ q, int ldq,
                             const float* __restrict__ kr, int ldk,
                             const float* __restrict__ prel,
                             float* __restrict__ alpha, float* __restrict__ ssum,
                             int E)
{
    int gt = blockIdx.x * blockDim.x + threadIdx.x;
    int e = gt >> 5;
    if (e >= E) return;
    int lane = threadIdx.x & 31;
    int s = __ldg(&src[e]), d = __ldg(&dst[e]);
    float4 qv = *reinterpret_cast<const float4*>(q + (size_t)d * ldq + lane * 4);
    float4 kv = *reinterpret_cast<const float4*>(kr + (size_t)s * ldk + lane * 4);
    float acc = qv.x * kv.x + qv.y * kv.y + qv.z * kv.z + qv.w * kv.w;
    acc += __shfl_xor_sync(0xffffffffu, acc, 1);
    acc += __shfl_xor_sync(0xffffffffu, acc, 2);
    acc += __shfl_xor_sync(0xffffffffu, acc, 4);
    if ((lane & 7) == 0) {
        int h = lane >> 3;
        float a = acc * __ldg(&prel[h]) * 0.17677669529663689f; // 1/sqrt(32)
        float ex = expf(a);
        alpha[(size_t)e * NH + h] = ex;
        atomicAdd(&ssum[(size_t)d * NH + h], ex);
    }
}

__global__ void edge_msg_k(const int* __restrict__ src, const int* __restrict__ dst,
                           const float* __restrict__ vr, int ldv,
                           const float* __restrict__ alpha,
                           const float* __restrict__ ssum,
                           float* __restrict__ agg, int E)
{
    int gt = blockIdx.x * blockDim.x + threadIdx.x;
    int e = gt >> 5;
    if (e >= E) return;
    int lane = threadIdx.x & 31;
    int s = __ldg(&src[e]), d = __ldg(&dst[e]);
    int h = lane >> 3;
    float coef = alpha[(size_t)e * NH + h] / (ssum[(size_t)d * NH + h] + 1e-16f);
    float4 v = *reinterpret_cast<const float4*>(vr + (size_t)s * ldv + lane * 4);
    float* p = agg + (size_t)d * HID + lane * 4;
    asm volatile("red.global.add.v4.f32 [%0], {%1,%2,%3,%4};"
                 :: "l"(p), "f"(v.x * coef), "f"(v.y * coef),
                    "f"(v.z * coef), "f"(v.w * coef)
                 : "memory");
}

// ---------------------------------------------------------------------------
// Host orchestration
// ---------------------------------------------------------------------------
extern "C" void kernel_launch(void* const* d_in, const int* in_sizes, int n_in,
                              void* d_out, int out_size)
{
    const float* x0   = (const float*)d_in[0];
    const float* x1   = (const float*)d_in[1];
    const int* srcp[3] = {(const int*)d_in[2], (const int*)d_in[4], (const int*)d_in[6]};
    const int* dstp[3] = {(const int*)d_in[3], (const int*)d_in[5], (const int*)d_in[7]};
    const int  Ecnt[3] = {in_sizes[2], in_sizes[4], in_sizes[6]};
    const float* W_in = (const float*)d_in[8];
    const float* b_in = (const float*)d_in[9];
    const float* Wk   = (const float*)d_in[10];
    const float* bk   = (const float*)d_in[11];
    const float* Wq   = (const float*)d_in[12];
    const float* bq   = (const float*)d_in[13];
    const float* Wv   = (const float*)d_in[14];
    const float* bv   = (const float*)d_in[15];
    const float* Wa   = (const float*)d_in[16];
    const float* ba   = (const float*)d_in[17];
    const float* skip = (const float*)d_in[18];
    const float* a_rel = (const float*)d_in[19];
    const float* m_rel = (const float*)d_in[20];
    const float* p_rel = (const float*)d_in[21];

    float* out = (float*)d_out;
    const int OW = HID * (NL + 1);       // 384
    float* y0 = out;
    float* y1 = out + (size_t)N0 * OW;

    float *qkv0, *qkv1, *agg, *alpha, *ssum, *wcat0, *wcat1, *bcat0, *bcat1;
    cudaGetSymbolAddress((void**)&qkv0,  g_qkv0);
    cudaGetSymbolAddress((void**)&qkv1,  g_qkv1);
    cudaGetSymbolAddress((void**)&agg,   g_agg);
    cudaGetSymbolAddress((void**)&alpha, g_alpha);
    cudaGetSymbolAddress((void**)&ssum,  g_ssum);
    cudaGetSymbolAddress((void**)&wcat0, g_wcat0);
    cudaGetSymbolAddress((void**)&wcat1, g_wcat1);
    cudaGetSymbolAddress((void**)&bcat0, g_bcat0);
    cudaGetSymbolAddress((void**)&bcat1, g_bcat1);

    cudaFuncSetAttribute(gemm_tc<0>, cudaFuncAttributeMaxDynamicSharedMemorySize, GEMM_SMEM);
    cudaFuncSetAttribute(gemm_tc<1>, cudaFuncAttributeMaxDynamicSharedMemorySize, GEMM_SMEM);
    cudaFuncSetAttribute(gemm_tc<2>, cudaFuncAttributeMaxDynamicSharedMemorySize, GEMM_SMEM);

    const int etD[3] = {1, 0, 1};
    const int Ncnt[2] = {N0, N1};

    const dim3 g0((N0 + GBM - 1) / GBM);
    const dim3 g1((N1 + GBM - 1) / GBM);

    // ---- input projection
    gemm_tc<1><<<g0, 256, GEMM_SMEM>>>(x0, HID, W_in, HID, b_in, y0, OW, N0, nullptr, 0, nullptr);
    gemm_tc<1><<<g1, 256, GEMM_SMEM>>>(x1, HID, W_in + HID * HID, HID, b_in + HID,
                                       y1, OW, N1, nullptr, 0, nullptr);

    for (int l = 0; l < NL; l++) {
        const float* h0 = y0 + l * HID;  // lda = OW
        const float* h1 = y1 + l * HID;

        // ---- fused weight prep
        WPrep8 P;
        const float* WkL0 = Wk + (size_t)(l * 2 + 0) * HID * HID;
        const float* WkL1 = Wk + (size_t)(l * 2 + 1) * HID * HID;
        const float* WvL0 = Wv + (size_t)(l * 2 + 0) * HID * HID;
        const float* WvL1 = Wv + (size_t)(l * 2 + 1) * HID * HID;
        const float* ar0 = a_rel + (size_t)(l * 3 + 0) * NH * HD * HD;
        const float* ar1 = a_rel + (size_t)(l * 3 + 1) * NH * HD * HD;
        const float* ar2 = a_rel + (size_t)(l * 3 + 2) * NH * HD * HD;
        const float* mr0 = m_rel + (size_t)(l * 3 + 0) * NH * HD * HD;
        const float* mr1 = m_rel + (size_t)(l * 3 + 1) * NH * HD * HD;
        const float* mr2 = m_rel + (size_t)(l * 3 + 2) * NH * HD * HD;
        P.s[0] = {Wq + (size_t)(l*2+0)*HID*HID, bq + (l*2+0)*HID, nullptr, wcat0,       bcat0,       LD0};
        P.s[1] = {WkL0, bk + (l*2+0)*HID, ar0, wcat0 + 128, bcat0 + 128, LD0};
        P.s[2] = {WvL0, bv + (l*2+0)*HID, mr0, wcat0 + 256, bcat0 + 256, LD0};
        P.s[3] = {Wq + (size_t)(l*2+1)*HID*HID, bq + (l*2+1)*HID, nullptr, wcat1,       bcat1,       LD1};
        P.s[4] = {WkL1, bk + (l*2+1)*HID, ar1, wcat1 + 128, bcat1 + 128, LD1};
        P.s[5] = {WvL1, bv + (l*2+1)*HID, mr1, wcat1 + 256, bcat1 + 256, LD1};
        P.s[6] = {WkL1, bk + (l*2+1)*HID, ar2, wcat1 + 384, bcat1 + 384, LD1};
        P.s[7] = {WvL1, bv + (l*2+1)*HID, mr2, wcat1 + 512, bcat1 + 512, LD1};
        prep_w_k<<<dim3(HID + 1, 8), HID>>>(P);

        // ---- fused projections
        gemm_tc<0><<<dim3(g0.x, LD0 / GBN), 256, GEMM_SMEM>>>(h0, OW, wcat0, LD0, bcat0,
                                                              qkv0, LD0, N0, nullptr, 0, nullptr);
        gemm_tc<0><<<dim3(g1.x, LD1 / GBN), 256, GEMM_SMEM>>>(h1, OW, wcat1, LD1, bcat1,
                                                              qkv1, LD1, N1, nullptr, 0, nullptr);

        cudaMemsetAsync(agg, 0, (size_t)(N0 + N1) * HID * sizeof(float), 0);

        const float* qd_tab[3]  = {qkv1,        qkv0,        qkv1};
        const int    ldq_tab[3] = {LD1,         LD0,         LD1};
        const float* kr_tab[3]  = {qkv0 + 128,  qkv1 + 128,  qkv1 + 384};
        const float* vr_tab[3]  = {qkv0 + 256,  qkv1 + 256,  qkv1 + 512};
        const int    lds_tab[3] = {LD0,         LD1,         LD1};

        for (int r = 0; r < 3; r++) {
            int dt = etD[r];
            int Nd = Ncnt[dt];
            int E  = Ecnt[r];

            cudaMemsetAsync(ssum, 0, (size_t)Nd * NH * sizeof(float), 0);

            float* aggd = (dt == 0) ? agg : agg + (size_t)N0 * HID;
            const float* pr = p_rel + (size_t)(l * 3 + r) * NH;

            int tpbE = 256;
            int nWT = E * 32;
            edge_alpha_k<<<(nWT + tpbE - 1) / tpbE, tpbE>>>(
                srcp[r], dstp[r], qd_tab[r], ldq_tab[r], kr_tab[r], lds_tab[r],
                pr, alpha, ssum, E);
            edge_msg_k<<<(nWT + tpbE - 1) / tpbE, tpbE>>>(
                srcp[r], dstp[r], vr_tab[r], lds_tab[r], alpha, ssum, aggd, E);
        }

        // ---- gelu(agg) then output projection + skip blend
        int n4 = (N0 + N1) * HID / 4;
        gelu_k<<<(n4 + 255) / 256, 256>>>(agg, n4);

        gemm_tc<2><<<g0, 256, GEMM_SMEM>>>(agg, HID,
                                           Wa + (size_t)(l * 2 + 0) * HID * HID, HID,
                                           ba + (l * 2 + 0) * HID,
                                           y0 + (l + 1) * HID, OW, N0,
                                           h0, OW, skip + l * 2 + 0);
        gemm_tc<2><<<g1, 256, GEMM_SMEM>>>(agg + (size_t)N0 * HID, HID,
                                           Wa + (size_t)(l * 2 + 1) * HID * HID, HID,
                                           ba + (l * 2 + 1) * HID,
                                           y1 + (l + 1) * HID, OW, N1,
                                           h1, OW, skip + l * 2 + 1);
    }
}